// round 16
// baseline (speedup 1.0000x reference)
#include <cuda_runtime.h>
#include <cuda_bf16.h>

// Final form: R13 (best: 35.296us wall, 30.2us cold) + evict-first L2 policy
// on the bulk-async output drain. Proven direct loads (MLP=4), smem-staged
// output, one cp.async.bulk per block through the TMA/bulk engine, with the
// write-once 96MB output stream marked evict_first so it passes through L2
// without displacing input lines (the only L2 hint that ever measured a win).

constexpr int TPB = 256;

__global__ __launch_bounds__(TPB)
void gaussian_cov_kernel(const float* __restrict__ scaling,
                         const float4* __restrict__ rot,
                         float* __restrict__ out,
                         int n)
{
    __shared__ alignas(128) float s_out[6 * TPB];  // 6 KB staged output

    int tid = threadIdx.x;
    int i = blockIdx.x * TPB + tid;
    bool full_block = (blockIdx.x + 1) * TPB <= n;  // uniform per block

    if (i < n) {
        // ---- proven direct load path (MLP=4): 3x LDG.32 + 1x LDG.128 ----
        float a0 = scaling[3 * i + 0];
        float a1 = scaling[3 * i + 1];
        float a2 = scaling[3 * i + 2];
        float4 q = rot[i];

        // s^2 = exp(2*raw): squaring folded into exponent
        float s0 = __expf(a0 + a0);
        float s1 = __expf(a1 + a1);
        float s2 = __expf(a2 + a2);

        float inv = rsqrtf(q.x * q.x + q.y * q.y + q.z * q.z + q.w * q.w);
        float w = q.x * inv, x = q.y * inv, y = q.z * inv, z = q.w * inv;

        float r00 = 1.0f - 2.0f * (y * y + z * z);
        float r01 = 2.0f * (x * y - w * z);
        float r02 = 2.0f * (x * z + w * y);
        float r10 = 2.0f * (x * y + w * z);
        float r11 = 1.0f - 2.0f * (x * x + z * z);
        float r12 = 2.0f * (y * z - w * x);
        float r20 = 2.0f * (x * z - w * y);
        float r21 = 2.0f * (y * z + w * x);
        float r22 = 1.0f - 2.0f * (x * x + y * y);

        float c00 = r00 * r00 * s0 + r01 * r01 * s1 + r02 * r02 * s2;
        float c01 = r00 * r10 * s0 + r01 * r11 * s1 + r02 * r12 * s2;
        float c02 = r00 * r20 * s0 + r01 * r21 * s1 + r02 * r22 * s2;
        float c11 = r10 * r10 * s0 + r11 * r11 * s1 + r12 * r12 * s2;
        float c12 = r10 * r20 * s0 + r11 * r21 * s1 + r12 * r22 * s2;
        float c22 = r20 * r20 * s0 + r21 * r21 * s1 + r22 * r22 * s2;

        if (full_block) {
            s_out[6 * tid + 0] = c00;
            s_out[6 * tid + 1] = c01;
            s_out[6 * tid + 2] = c02;
            s_out[6 * tid + 3] = c11;
            s_out[6 * tid + 4] = c12;
            s_out[6 * tid + 5] = c22;
        } else {
            // tail block: direct scalar stores (not hit for N=4M)
            out[6 * i + 0] = c00; out[6 * i + 1] = c01; out[6 * i + 2] = c02;
            out[6 * i + 3] = c11; out[6 * i + 4] = c12; out[6 * i + 5] = c22;
        }
    }

    if (full_block) {
        __syncthreads();
        if (tid == 0) {
            // smem generic-proxy writes must be visible to the async proxy
            asm volatile("fence.proxy.async.shared::cta;" ::: "memory");

            unsigned int smem_addr;
            asm("{ .reg .u64 t; cvta.to.shared.u64 t, %1; cvt.u32.u64 %0, t; }"
                : "=r"(smem_addr) : "l"(s_out));
            float* gp = out + (size_t)blockIdx.x * (6 * TPB);

            // Evict-first policy: output is write-once, keep it out of L2's way
            unsigned long long pol;
            asm volatile("createpolicy.fractional.L2::evict_first.b64 %0, 1.0;"
                         : "=l"(pol));

            // One 6KB bulk store per block via the async/TMA engine
            asm volatile(
                "cp.async.bulk.global.shared::cta.bulk_group.L2::cache_hint "
                "[%0], [%1], %2, %3;"
                :: "l"(gp), "r"(smem_addr),
                   "r"((int)(6 * TPB * sizeof(float))), "l"(pol)
                : "memory");
            asm volatile("cp.async.bulk.commit_group;" ::: "memory");
            // Smem is the source: must complete before the CTA exits
            asm volatile("cp.async.bulk.wait_group 0;" ::: "memory");
        }
    }
}

extern "C" void kernel_launch(void* const* d_in, const int* in_sizes, int n_in,
                              void* d_out, int out_size)
{
    const float*  scaling = (const float*)d_in[0];   // [N,3] float32
    const float4* rot     = (const float4*)d_in[1];  // [N,4] float32
    float*        out     = (float*)d_out;           // [N,6] float32

    int n = in_sizes[0] / 3;  // N
    int blocks = (n + TPB - 1) / TPB;
    gaussian_cov_kernel<<<blocks, TPB>>>(scaling, rot, out, n);
}